// round 16
// baseline (speedup 1.0000x reference)
#include <cuda_runtime.h>
#include <cuda_fp16.h>
#include <math.h>

#define BB 2
#define HH 16
#define SS 2048
#define DD 1024
#define HD 64
#define MM (BB*SS)          // 4096 rows

// Scratch (device globals)
__device__ __half g_q[BB*HH*SS*HD];   // [B,H,S,hd] fp16
__device__ __half g_k[BB*HH*SS*HD];   // [B,H,S,hd] fp16
__device__ __half g_v[BB*HH*HD*SS];   // [B,H,hd,S] fp16 (TRANSPOSED)
__device__ __half g_ao[MM*DD];        // attention output fp16
__device__ __half g_x[MM*DD];         // fp16 X
__device__ __half g_wa[3*DD*DD];      // W_attn^T  [n=3072][k=1024] fp16
__device__ __half g_wp[DD*DD];        // W_proj^T  [n=1024][k=1024] fp16
__device__ float2 g_ml[BB*HH*SS];     // per-row (m, 1/l)

// ---------------------------------------------------------------------------
// helpers
// ---------------------------------------------------------------------------
__device__ __forceinline__ void mma16(float* c,
                                      unsigned a0, unsigned a1, unsigned a2, unsigned a3,
                                      unsigned b0, unsigned b1) {
    asm volatile(
        "mma.sync.aligned.m16n8k16.row.col.f32.f16.f16.f32 "
        "{%0,%1,%2,%3},{%4,%5,%6,%7},{%8,%9},{%0,%1,%2,%3};"
        : "+f"(c[0]), "+f"(c[1]), "+f"(c[2]), "+f"(c[3])
        : "r"(a0), "r"(a1), "r"(a2), "r"(a3), "r"(b0), "r"(b1));
}
__device__ __forceinline__ void ldsm4(unsigned& r0, unsigned& r1, unsigned& r2, unsigned& r3,
                                      const void* p) {
    unsigned a = (unsigned)__cvta_generic_to_shared(p);
    asm volatile("ldmatrix.sync.aligned.m8n8.x4.shared.b16 {%0,%1,%2,%3}, [%4];"
                 : "=r"(r0), "=r"(r1), "=r"(r2), "=r"(r3) : "r"(a));
}
__device__ __forceinline__ void cpa16(const void* smem_dst, const void* gsrc) {
    unsigned s = (unsigned)__cvta_generic_to_shared(smem_dst);
    asm volatile("cp.async.cg.shared.global [%0], [%1], 16;" :: "r"(s), "l"(gsrc));
}
__device__ __forceinline__ void cpa_commit() {
    asm volatile("cp.async.commit_group;");
}
__device__ __forceinline__ void cpa_wait0() {
    asm volatile("cp.async.wait_group 0;");
}
__device__ __forceinline__ void stcs2(float* p, float a, float b) {
    asm volatile("st.global.cs.v2.f32 [%0], {%1,%2};" :: "l"(p), "f"(a), "f"(b));
}
__device__ __forceinline__ void stcs4(float* p, float4 v) {
    asm volatile("st.global.cs.v4.f32 [%0], {%1,%2,%3,%4};"
                 :: "l"(p), "f"(v.x), "f"(v.y), "f"(v.z), "f"(v.w));
}

// ---------------------------------------------------------------------------
// Fused preprocessing: one launch.
// ---------------------------------------------------------------------------
__global__ __launch_bounds__(256) void preproc(const float* __restrict__ X,
                                               const float* __restrict__ Wa,
                                               const float* __restrict__ Wp)
{
    __shared__ float ts[32][33];
    const int tx = threadIdx.x & 31, ty = threadIdx.x >> 5;
    const int idx = blockIdx.x;

    if (idx < 3072) {
        const int nb = (idx % 96) * 32, kb = (idx / 96) * 32;
#pragma unroll
        for (int i = 0; i < 4; i++)
            ts[ty + i * 8][tx] = Wa[(size_t)(kb + ty + i * 8) * 3072 + nb + tx];
        __syncthreads();
#pragma unroll
        for (int i = 0; i < 4; i++)
            g_wa[(size_t)(nb + ty + i * 8) * 1024 + kb + tx] =
                __float2half_rn(ts[tx][ty + i * 8]);
    } else if (idx < 4096) {
        const int w = idx - 3072;
        const int nb = (w % 32) * 32, kb = (w / 32) * 32;
#pragma unroll
        for (int i = 0; i < 4; i++)
            ts[ty + i * 8][tx] = Wp[(size_t)(kb + ty + i * 8) * 1024 + nb + tx];
        __syncthreads();
#pragma unroll
        for (int i = 0; i < 4; i++)
            g_wp[(size_t)(nb + ty + i * 8) * 1024 + kb + tx] =
                __float2half_rn(ts[tx][ty + i * 8]);
    } else {
        const int base = (idx - 4096) * 256 + threadIdx.x;
        for (int k = base; k < MM * DD / 4; k += 1024 * 256) {
            float4 v = ((const float4*)X)[k];
            ((__half2*)g_x)[k * 2    ] = __floats2half2_rn(v.x, v.y);
            ((__half2*)g_x)[k * 2 + 1] = __floats2half2_rn(v.z, v.w);
        }
    }
}

// ---------------------------------------------------------------------------
// fp16 GEMM core: C[128x128] tile, K-tile 64, 2-stage cp.async, ldmatrix.x4
// ---------------------------------------------------------------------------
#define TH 72
#define TH32 36
#define TSZ (128*TH)
#define GEMM_SMEM_BYTES (2 * 2 * TSZ * 2)

__device__ __forceinline__ void gemm128(const __half* __restrict__ Asrc, size_t a_stride,
                                        const __half* __restrict__ Bsrc, size_t b_stride,
                                        int bm, int bn, __half* sh, float acc[4][4][4])
{
    __half* Ah = sh;
    __half* Bh = sh + 2 * TSZ;

    const int tid  = threadIdx.x;
    const int NK = 16;

    auto stage = [&](int t) {
        const int k0 = t * 64;
        __half* An = Ah + (t & 1) * TSZ;
        __half* Bn = Bh + (t & 1) * TSZ;
#pragma unroll
        for (int i = 0; i < 4; i++) {
            int c = tid + i * 256;
            int row = c >> 3, cc = c & 7;
            cpa16(&An[row * TH + cc * 8], &Asrc[(size_t)(bm + row) * a_stride + k0 + cc * 8]);
            cpa16(&Bn[row * TH + cc * 8], &Bsrc[(size_t)(bn + row) * b_stride + k0 + cc * 8]);
        }
    };

    stage(0); cpa_commit();

    const int lane = tid & 31;
    const int wid  = tid >> 5;
    const int wm   = (wid >> 2) * 64;
    const int wn   = (wid & 3) * 32;
    const int q8   = lane >> 3;
    const int r8   = lane & 7;

    for (int kt = 0; kt < NK; kt++) {
        cpa_wait0();
        __syncthreads();
        if (kt + 1 < NK) {
            stage(kt + 1);
            cpa_commit();
        }

        const unsigned* A32 = (const unsigned*)(Ah + (kt & 1) * TSZ);
        const unsigned* B32 = (const unsigned*)(Bh + (kt & 1) * TSZ);
#pragma unroll
        for (int kc = 0; kc < 4; kc++) {
            const int kb = kc * 8;
            unsigned af[4][4], bf[4][2];
#pragma unroll
            for (int mi = 0; mi < 4; mi++) {
                const int row = wm + mi * 16 + (q8 & 1) * 8 + r8;
                const int col = kb + (q8 >> 1) * 4;
                ldsm4(af[mi][0], af[mi][1], af[mi][2], af[mi][3], A32 + row * TH32 + col);
            }
#pragma unroll
            for (int njp = 0; njp < 4; njp += 2) {
                const int row = wn + njp * 8 + (q8 >> 1) * 8 + r8;
                const int col = kb + (q8 & 1) * 4;
                ldsm4(bf[njp][0], bf[njp][1], bf[njp + 1][0], bf[njp + 1][1],
                      B32 + row * TH32 + col);
            }
#pragma unroll
            for (int mi = 0; mi < 4; mi++)
#pragma unroll
                for (int nj = 0; nj < 4; nj++)
                    mma16(acc[mi][nj], af[mi][0], af[mi][1], af[mi][2], af[mi][3],
                          bf[nj][0], bf[nj][1]);
        }
    }
}

// ---------------------------------------------------------------------------
// QKV GEMM: q/k [B,H,S,hd]; v TRANSPOSED [B,H,hd,S]
// ---------------------------------------------------------------------------
__global__ __launch_bounds__(256, 2) void qkv_gemm(const float* __restrict__ bias)
{
    extern __shared__ __half shq[];
    float acc[4][4][4];
#pragma unroll
    for (int mi = 0; mi < 4; mi++)
#pragma unroll
        for (int nj = 0; nj < 4; nj++)
#pragma unroll
            for (int t = 0; t < 4; t++) acc[mi][nj][t] = 0.f;

    const int bm = blockIdx.y * 128;
    const int bn = blockIdx.x * 128;
    gemm128(g_x, 1024, g_wa, 1024, bm, bn, shq, acc);

    const int lane = threadIdx.x & 31;
    const int wid  = threadIdx.x >> 5;
    const int g    = lane >> 2;
    const int tg   = lane & 3;
    const int wm   = (wid >> 2) * 64;
    const int wn   = (wid & 3) * 32;

#pragma unroll
    for (int mi = 0; mi < 4; mi++) {
#pragma unroll
        for (int nj = 0; nj < 4; nj++) {
#pragma unroll
            for (int t = 0; t < 4; t++) {
                const int m = bm + wm + mi * 16 + g + ((t >= 2) ? 8 : 0);
                const int n = bn + wn + nj * 8 + 2 * tg + (t & 1);
                const float v = acc[mi][nj][t] + bias[n];
                const int bidx = m >> 11;
                const int s = m & 2047;
                const int which = n >> 10;
                const int jj = n & 1023;
                const int h = jj >> 6;
                const int d = jj & 63;
                if (which == 0)
                    g_q[(size_t)((bidx * HH + h) * SS + s) * HD + d] = __float2half_rn(v);
                else if (which == 1)
                    g_k[(size_t)((bidx * HH + h) * SS + s) * HD + d] = __float2half_rn(v);
                else
                    g_v[(size_t)((bidx * HH + h) * HD + d) * SS + s] = __float2half_rn(v);
            }
        }
    }
}

// ---------------------------------------------------------------------------
// Flash attention pass 1 only: O, m, 1/l. LPT. (R12/R14 structure, no zeros)
// ---------------------------------------------------------------------------
#define PS_H 136
#define PS_H32 68
#define PSSZ (128*PS_H)
#define KH 72
#define KH32 36
#define KSZH (128*KH)
#define VT_H 136
#define VT_H32 68
#define VTSZ (64*VT_H)
#define ATT_SMEM_BYTES ((PSSZ + 2*KSZH + 2*VTSZ) * 2)

__global__ __launch_bounds__(256, 2) void attn_kernel()
{
    extern __shared__ __half smh[];
    __half* Ps = smh;                     // [128][PS_H]
    __half* Kh = smh + PSSZ;              // [2][128][KH]
    __half* VT = Kh + 2 * KSZH;           // [2][64][VT_H]

    const int tid  = threadIdx.x;
    const int lane = tid & 31;
    const int wid  = tid >> 5;
    const int g    = lane >> 2;
    const int tg   = lane & 3;
    const int qw   = wid * 16;
    const int q8   = lane >> 3;
    const int r8   = lane & 7;

    const int b  = blockIdx.z;
    const int h  = blockIdx.y;
    const int qt = (gridDim.x - 1) - blockIdx.x;   // LPT
    const int q0 = qt * 128;

    const __half* Qbh = g_q + (size_t)((b * HH + h) * SS) * HD;
    const __half* Kbh = g_k + (size_t)((b * HH + h) * SS) * HD;
    const __half* Vbt = g_v + (size_t)((b * HH + h) * HD) * SS;

#pragma unroll
    for (int i = 0; i < 4; i++) {
        int c = tid + i * 256;
        int row = c >> 3, cc = c & 7;
        cpa16(&Kh[row * KH + cc * 8], &Kbh[(size_t)row * HD + cc * 8]);
    }
#pragma unroll
    for (int i = 0; i < 4; i++) {
        int c = tid + i * 256;
        int row = c >> 4, cc = c & 15;
        cpa16(&VT[row * VT_H + cc * 8], &Vbt[(size_t)row * SS + cc * 8]);
    }
    cpa_commit();

    unsigned qa[4][4];
    {
        const unsigned* q0p = (const unsigned*)(Qbh + (size_t)(q0 + qw + g) * HD);
        const unsigned* q1p = (const unsigned*)(Qbh + (size_t)(q0 + qw + g + 8) * HD);
#pragma unroll
        for (int kc = 0; kc < 4; kc++) {
            qa[kc][0] = q0p[kc * 8 + tg    ];
            qa[kc][1] = q1p[kc * 8 + tg    ];
            qa[kc][2] = q0p[kc * 8 + 4 + tg];
            qa[kc][3] = q1p[kc * 8 + 4 + tg];
        }
    }

    float m0 = -1e30f, m1 = -1e30f, l0 = 0.f, l1 = 0.f;
    float o[8][4];
#pragma unroll
    for (int nf = 0; nf < 8; nf++)
#pragma unroll
        for (int t = 0; t < 4; t++) o[nf][t] = 0.f;

    const int nkt  = qt + 1;
    const int row0 = q0 + qw + g;
    const int row1 = row0 + 8;

    for (int kt = 0; kt < nkt; kt++) {
        cpa_wait0();
        __syncthreads();

        if (kt + 1 < nkt) {
            const int nb = (kt + 1) * 128;
            __half* Kn = Kh + ((kt + 1) & 1) * KSZH;
            __half* Vn = VT + ((kt + 1) & 1) * VTSZ;
#pragma unroll
            for (int i = 0; i < 4; i++) {
                int c = tid + i * 256;
                int row = c >> 3, cc = c & 7;
                cpa16(&Kn[row * KH + cc * 8], &Kbh[(size_t)(nb + row) * HD + cc * 8]);
            }
#pragma unroll
            for (int i = 0; i < 4; i++) {
                int c = tid + i * 256;
                int row = c >> 4, cc = c & 15;
                cpa16(&Vn[row * VT_H + cc * 8], &Vbt[(size_t)row * SS + nb + cc * 8]);
            }
            cpa_commit();
        }

        const unsigned* K32 = (const unsigned*)(Kh + (kt & 1) * KSZH);
        const int kbase = kt * 128;

        float s[16][4];
#pragma unroll
        for (int nf = 0; nf < 16; nf++)
#pragma unroll
            for (int t = 0; t < 4; t++) s[nf][t] = 0.f;
#pragma unroll
        for (int kc = 0; kc < 4; kc++) {
#pragma unroll
            for (int nfp = 0; nfp < 16; nfp += 2) {
                unsigned b00, b01, b10, b11;
                const int row = nfp * 8 + (q8 >> 1) * 8 + r8;
                const int col = kc * 8 + (q8 & 1) * 4;
                ldsm4(b00, b01, b10, b11, K32 + row * KH32 + col);
                mma16(s[nfp    ], qa[kc][0], qa[kc][1], qa[kc][2], qa[kc][3], b00, b01);
                mma16(s[nfp + 1], qa[kc][0], qa[kc][1], qa[kc][2], qa[kc][3], b10, b11);
            }
        }

        const bool diag = (kt == qt);
        float mx0 = -1e30f, mx1 = -1e30f;
#pragma unroll
        for (int nf = 0; nf < 16; nf++) {
            const int col = kbase + nf * 8 + 2 * tg;
            float v0 = s[nf][0] * 0.125f;
            float v1 = s[nf][1] * 0.125f;
            float v2 = s[nf][2] * 0.125f;
            float v3 = s[nf][3] * 0.125f;
            if (diag) {
                if (col     > row0) v0 = -1e30f;
                if (col + 1 > row0) v1 = -1e30f;
                if (col     > row1) v2 = -1e30f;
                if (col + 1 > row1) v3 = -1e30f;
            }
            s[nf][0] = v0; s[nf][1] = v1; s[nf][2] = v2; s[nf][3] = v3;
            mx0 = fmaxf(mx0, fmaxf(v0, v1));
            mx1 = fmaxf(mx1, fmaxf(v2, v3));
        }
        mx0 = fmaxf(mx0, __shfl_xor_sync(0xffffffffu, mx0, 1));
        mx0 = fmaxf(mx0, __shfl_xor_sync(0xffffffffu, mx0, 2));
        mx1 = fmaxf(mx1, __shfl_xor_sync(0xffffffffu, mx1, 1));
        mx1 = fmaxf(mx1, __shfl_xor_sync(0xffffffffu, mx1, 2));

        const float mn0 = fmaxf(m0, mx0);
        const float mn1 = fmaxf(m1, mx1);
        const float al0 = __expf(m0 - mn0);
        const float al1 = __expf(m1 - mn1);

        float rs0 = 0.f, rs1 = 0.f;
        __half2* Pp = (__half2*)Ps;
#pragma unroll
        for (int nf = 0; nf < 16; nf++) {
            const float p0 = __expf(s[nf][0] - mn0);
            const float p1 = __expf(s[nf][1] - mn0);
            const float p2 = __expf(s[nf][2] - mn1);
            const float p3 = __expf(s[nf][3] - mn1);
            rs0 += p0 + p1;
            rs1 += p2 + p3;
            Pp[(qw + g    ) * (PS_H/2) + nf * 4 + tg] = __floats2half2_rn(p0, p1);
            Pp[(qw + g + 8) * (PS_H/2) + nf * 4 + tg] = __floats2half2_rn(p2, p3);
        }
        rs0 += __shfl_xor_sync(0xffffffffu, rs0, 1);
        rs0 += __shfl_xor_sync(0xffffffffu, rs0, 2);
        rs1 += __shfl_xor_sync(0xffffffffu, rs1, 1);
        rs1 += __shfl_xor_sync(0xffffffffu, rs1, 2);

        m0 = mn0; m1 = mn1;
        l0 = l0 * al0 + rs0;
        l1 = l1 * al1 + rs1;
#pragma unroll
        for (int nf = 0; nf < 8; nf++) {
            o[nf][0] *= al0; o[nf][1] *= al0;
            o[nf][2] *= al1; o[nf][3] *= al1;
        }

        const unsigned* P32  = (const unsigned*)Ps;
        const unsigned* VT32 = (const unsigned*)(VT + (kt & 1) * VTSZ);
#pragma unroll
        for (int kc = 0; kc < 8; kc++) {
            unsigned a0, a1, a2, a3;
            {
                const int row = qw + (q8 & 1) * 8 + r8;
                const int col = kc * 8 + (q8 >> 1) * 4;
                ldsm4(a0, a1, a2, a3, P32 + row * PS_H32 + col);
            }
#pragma unroll
            for (int nfp = 0; nfp < 8; nfp += 2) {
                unsigned b00, b01, b10, b11;
                const int row = nfp * 8 + (q8 >> 1) * 8 + r8;
                const int col = kc * 8 + (q8 & 1) * 4;
                ldsm4(b00, b01, b10, b11, VT32 + row * VT_H32 + col);
                mma16(o[nfp    ], a0, a1, a2, a3, b00, b01);
                mma16(o[nfp + 1], a0, a1, a2, a3, b10, b11);
            }
        }
    }

    const float il0 = 1.0f / l0;
    const float il1 = 1.0f / l1;
    {
        const int orow = b * SS + q0 + qw + g;
#pragma unroll
        for (int nf = 0; nf < 8; nf++) {
            const int col = h * HD + nf * 8 + 2 * tg;
            __half2* d0 = (__half2*)&g_ao[(size_t)orow * DD + col];
            __half2* d1 = (__half2*)&g_ao[(size_t)(orow + 8) * DD + col];
            *d0 = __floats2half2_rn(o[nf][0] * il0, o[nf][1] * il0);
            *d1 = __floats2half2_rn(o[nf][2] * il1, o[nf][3] * il1);
        }
        if (tg == 0) {
            const size_t mlbase = (size_t)(b * HH + h) * SS;
            g_ml[mlbase + q0 + qw + g    ] = make_float2(m0, il0);
            g_ml[mlbase + q0 + qw + g + 8] = make_float2(m1, il1);
        }
    }
}

// ---------------------------------------------------------------------------
// Epilogue: CTA 0..255 = proj tiles; 256..8447 = weight tiles (zero / recompute)
// __launch_bounds__(256,3): 3 CTAs/SM; weight branch restructured into two
// 8-nf halves to fit the 84-reg cap without spilling.
// ---------------------------------------------------------------------------
__global__ __launch_bounds__(256, 3) void epilogue(const float* __restrict__ bias,
                                                   float* __restrict__ out)
{
    extern __shared__ __half shq[];
    const int tid  = threadIdx.x;
    const int lane = tid & 31;
    const int wid  = tid >> 5;
    const int g    = lane >> 2;
    const int tg   = lane & 3;
    const int idx  = blockIdx.x;

    if (idx < 256) {
        float acc[4][4][4];
#pragma unroll
        for (int mi = 0; mi < 4; mi++)
#pragma unroll
            for (int nj = 0; nj < 4; nj++)
#pragma unroll
                for (int t = 0; t < 4; t++) acc[mi][nj][t] = 0.f;

        const int bm = (idx >> 3) * 128;
        const int bn = (idx & 7) * 128;
        gemm128(g_ao, 1024, g_wp, 1024, bm, bn, shq, acc);

        const int wm = (wid >> 2) * 64;
        const int wn = (wid & 3) * 32;
#pragma unroll
        for (int mi = 0; mi < 4; mi++) {
#pragma unroll
            for (int nj = 0; nj < 4; nj++) {
#pragma unroll
                for (int t = 0; t < 4; t++) {
                    const int m = bm + wm + mi * 16 + g + ((t >= 2) ? 8 : 0);
                    const int n = bn + wn + nj * 8 + 2 * tg + (t & 1);
                    out[(size_t)m * DD + n] = acc[mi][nj][t] + bias[n];
                }
            }
        }
        return;
    }

    const int w  = idx - 256;
    const int bh = w >> 8;
    const int t8 = w & 255;
    const int qt = t8 >> 4;
    const int kt = t8 & 15;
    const int b  = bh >> 4;
    const int h  = bh & 15;
    const int q0 = qt * 128;
    const int kbase = kt * 128;

    float* attn = out + (size_t)MM * DD;
    float* dst = attn + ((size_t)((b * HH + h) * SS) + q0) * SS + kbase;

    if (kt > qt) {
        const float4 z = make_float4(0.f, 0.f, 0.f, 0.f);
#pragma unroll
        for (int i = 0; i < 16; i++) {
            int c = tid + i * 256;
            int row = c >> 5, c4 = c & 31;
            stcs4(&dst[(size_t)row * SS + c4 * 4], z);
        }
        return;
    }

    const __half* Kbh = g_k + (size_t)((b * HH + h) * SS) * HD;
    __half* Kh = shq;
#pragma unroll
    for (int i = 0; i < 4; i++) {
        int c = tid + i * 256;
        int row = c >> 3, cc = c & 7;
        cpa16(&Kh[row * KH + cc * 8], &Kbh[(size_t)(kbase + row) * HD + cc * 8]);
    }
    cpa_commit();

    const __half* Qbh = g_q + (size_t)((b * HH + h) * SS) * HD;
    const int qw = wid * 16;
    unsigned qa[4][4];
    {
        const unsigned* q0p = (const unsigned*)(Qbh + (size_t)(q0 + qw + g) * HD);
        const unsigned* q1p = (const unsigned*)(Qbh + (size_t)(q0 + qw + g + 8) * HD);
#pragma unroll
        for (int kc = 0; kc < 4; kc++) {
            qa[kc][0] = q0p[kc * 8 + tg    ];
            qa[kc][1] = q1p[kc * 8 + tg    ];
            qa[kc][2] = q0p[kc * 8 + 4 + tg];
            qa[kc][3] = q1p[kc * 8 + 4 + tg];
        }
    }

    const size_t mlbase = (size_t)(b * HH + h) * SS;
    const float2 ml0 = g_ml[mlbase + q0 + qw + g    ];
    const float2 ml1 = g_ml[mlbase + q0 + qw + g + 8];

    cpa_wait0();
    __syncthreads();

    const int q8 = lane >> 3;
    const int r8 = lane & 7;
    const unsigned* K32 = (const unsigned*)Kh;

    const bool diag = (kt == qt);
    const int row0 = q0 + qw + g;
    const int row1 = row0 + 8;
    float* w0p = dst + (size_t)(qw + g) * SS;
    float* w1p = dst + (size_t)(qw + g + 8) * SS;

    // two 8-nf halves: cuts live score registers from 64 to 32
#pragma unroll
    for (int half = 0; half < 2; half++) {
        float s[8][4];
#pragma unroll
        for (int nf = 0; nf < 8; nf++)
#pragma unroll
            for (int t = 0; t < 4; t++) s[nf][t] = 0.f;
#pragma unroll
        for (int kc = 0; kc < 4; kc++) {
#pragma unroll
            for (int nfp = 0; nfp < 8; nfp += 2) {
                unsigned b00, b01, b10, b11;
                const int row = (half * 8 + nfp) * 8 + (q8 >> 1) * 8 + r8;
                const int col = kc * 8 + (q8 & 1) * 4;
                ldsm4(b00, b01, b10, b11, K32 + row * KH32 + col);
                mma16(s[nfp    ], qa[kc][0], qa[kc][1], qa[kc][2], qa[kc][3], b00, b01);
                mma16(s[nfp + 1], qa[kc][0], qa[kc][1], qa[kc][2], qa[kc][3], b10, b11);
            }
        }
#pragma unroll
        for (int nf = 0; nf < 8; nf++) {
            const int coll = (half * 8 + nf) * 8 + 2 * tg;
            const int col  = kbase + coll;
            float w0 = __expf(s[nf][0] * 0.125f - ml0.x) * ml0.y;
            float w1 = __expf(s[nf][1] * 0.125f - ml0.x) * ml0.y;
            float w2 = __expf(s[nf][2] * 0.125f - ml1.x) * ml1.y;
            float w3 = __expf(s[nf][3] * 0.125f - ml1.x) * ml1.y;
            if (diag) {
                if (col     > row0) w0 = 0.f;
                if (col + 1 > row0) w1 = 0.f;
                if (col     > row1) w2 = 0.f;
                if (col + 1 > row1) w3 = 0.f;
            }
            stcs2(&w0p[coll], w0, w1);
            stcs2(&w1p[coll], w2, w3);
        }
    }
}

// ---------------------------------------------------------------------------
extern "C" void kernel_launch(void* const* d_in, const int* in_sizes, int n_in,
                              void* d_out, int out_size)
{
    const float* x      = (const float*)d_in[0];
    const float* W_attn = (const float*)d_in[1];
    const float* b_attn = (const float*)d_in[2];
    const float* W_proj = (const float*)d_in[3];
    const float* b_proj = (const float*)d_in[4];
    float* out = (float*)d_out;

    cudaFuncSetAttribute(qkv_gemm,
                         cudaFuncAttributeMaxDynamicSharedMemorySize, GEMM_SMEM_BYTES);
    cudaFuncSetAttribute(epilogue,
                         cudaFuncAttributeMaxDynamicSharedMemorySize, GEMM_SMEM_BYTES);
    cudaFuncSetAttribute(attn_kernel,
                         cudaFuncAttributeMaxDynamicSharedMemorySize, ATT_SMEM_BYTES);

    preproc<<<5120, 256>>>(x, W_attn, W_proj);
    qkv_gemm<<<dim3(24, 32), 256, GEMM_SMEM_BYTES>>>(b_attn);
    attn_kernel<<<dim3(SS / 128, HH, BB), 256, ATT_SMEM_BYTES>>>();
    epilogue<<<8448, 256, GEMM_SMEM_BYTES>>>(b_proj, out);
}

// round 17
// speedup vs baseline: 1.0688x; 1.0688x over previous
#include <cuda_runtime.h>
#include <cuda_fp16.h>
#include <math.h>

#define BB 2
#define HH 16
#define SS 2048
#define DD 1024
#define HD 64
#define MM (BB*SS)          // 4096 rows

// Scratch (device globals)
__device__ __half g_q[BB*HH*SS*HD];   // [B,H,S,hd] fp16
__device__ __half g_k[BB*HH*SS*HD];   // [B,H,S,hd] fp16
__device__ __half g_v[BB*HH*HD*SS];   // [B,H,hd,S] fp16 (TRANSPOSED)
__device__ __half g_ao[MM*DD];        // attention output fp16
__device__ __half g_x[MM*DD];         // fp16 X
__device__ __half g_wa[3*DD*DD];      // W_attn^T  [n=3072][k=1024] fp16
__device__ __half g_wp[DD*DD];        // W_proj^T  [n=1024][k=1024] fp16
__device__ float2 g_ml[BB*HH*SS];     // per-row (m, 1/l)

// ---------------------------------------------------------------------------
// helpers
// ---------------------------------------------------------------------------
__device__ __forceinline__ void mma16(float* c,
                                      unsigned a0, unsigned a1, unsigned a2, unsigned a3,
                                      unsigned b0, unsigned b1) {
    asm volatile(
        "mma.sync.aligned.m16n8k16.row.col.f32.f16.f16.f32 "
        "{%0,%1,%2,%3},{%4,%5,%6,%7},{%8,%9},{%0,%1,%2,%3};"
        : "+f"(c[0]), "+f"(c[1]), "+f"(c[2]), "+f"(c[3])
        : "r"(a0), "r"(a1), "r"(a2), "r"(a3), "r"(b0), "r"(b1));
}
__device__ __forceinline__ void ldsm4(unsigned& r0, unsigned& r1, unsigned& r2, unsigned& r3,
                                      const void* p) {
    unsigned a = (unsigned)__cvta_generic_to_shared(p);
    asm volatile("ldmatrix.sync.aligned.m8n8.x4.shared.b16 {%0,%1,%2,%3}, [%4];"
                 : "=r"(r0), "=r"(r1), "=r"(r2), "=r"(r3) : "r"(a));
}
__device__ __forceinline__ void cpa16(const void* smem_dst, const void* gsrc) {
    unsigned s = (unsigned)__cvta_generic_to_shared(smem_dst);
    asm volatile("cp.async.cg.shared.global [%0], [%1], 16;" :: "r"(s), "l"(gsrc));
}
__device__ __forceinline__ void cpa_commit() {
    asm volatile("cp.async.commit_group;");
}
__device__ __forceinline__ void cpa_wait0() {
    asm volatile("cp.async.wait_group 0;");
}
__device__ __forceinline__ void cpa_wait1() {
    asm volatile("cp.async.wait_group 1;");
}
__device__ __forceinline__ void stcs2(float* p, float a, float b) {
    asm volatile("st.global.cs.v2.f32 [%0], {%1,%2};" :: "l"(p), "f"(a), "f"(b));
}
__device__ __forceinline__ void stcs4(float* p, float4 v) {
    asm volatile("st.global.cs.v4.f32 [%0], {%1,%2,%3,%4};"
                 :: "l"(p), "f"(v.x), "f"(v.y), "f"(v.z), "f"(v.w));
}

// ---------------------------------------------------------------------------
// Fused preprocessing: one launch.
// ---------------------------------------------------------------------------
__global__ __launch_bounds__(256) void preproc(const float* __restrict__ X,
                                               const float* __restrict__ Wa,
                                               const float* __restrict__ Wp)
{
    __shared__ float ts[32][33];
    const int tx = threadIdx.x & 31, ty = threadIdx.x >> 5;
    const int idx = blockIdx.x;

    if (idx < 3072) {
        const int nb = (idx % 96) * 32, kb = (idx / 96) * 32;
#pragma unroll
        for (int i = 0; i < 4; i++)
            ts[ty + i * 8][tx] = Wa[(size_t)(kb + ty + i * 8) * 3072 + nb + tx];
        __syncthreads();
#pragma unroll
        for (int i = 0; i < 4; i++)
            g_wa[(size_t)(nb + ty + i * 8) * 1024 + kb + tx] =
                __float2half_rn(ts[tx][ty + i * 8]);
    } else if (idx < 4096) {
        const int w = idx - 3072;
        const int nb = (w % 32) * 32, kb = (w / 32) * 32;
#pragma unroll
        for (int i = 0; i < 4; i++)
            ts[ty + i * 8][tx] = Wp[(size_t)(kb + ty + i * 8) * 1024 + nb + tx];
        __syncthreads();
#pragma unroll
        for (int i = 0; i < 4; i++)
            g_wp[(size_t)(nb + ty + i * 8) * 1024 + kb + tx] =
                __float2half_rn(ts[tx][ty + i * 8]);
    } else {
        const int base = (idx - 4096) * 256 + threadIdx.x;
        for (int k = base; k < MM * DD / 4; k += 1024 * 256) {
            float4 v = ((const float4*)X)[k];
            ((__half2*)g_x)[k * 2    ] = __floats2half2_rn(v.x, v.y);
            ((__half2*)g_x)[k * 2 + 1] = __floats2half2_rn(v.z, v.w);
        }
    }
}

// ---------------------------------------------------------------------------
// fp16 GEMM core: C[128x128] tile, K-tile 64, 2-stage cp.async, ldmatrix.x4
// ---------------------------------------------------------------------------
#define TH 72
#define TH32 36
#define TSZ (128*TH)
#define GEMM_SMEM_BYTES (2 * 2 * TSZ * 2)

__device__ __forceinline__ void gemm128(const __half* __restrict__ Asrc, size_t a_stride,
                                        const __half* __restrict__ Bsrc, size_t b_stride,
                                        int bm, int bn, __half* sh, float acc[4][4][4])
{
    __half* Ah = sh;
    __half* Bh = sh + 2 * TSZ;

    const int tid  = threadIdx.x;
    const int NK = 16;

    auto stage = [&](int t) {
        const int k0 = t * 64;
        __half* An = Ah + (t & 1) * TSZ;
        __half* Bn = Bh + (t & 1) * TSZ;
#pragma unroll
        for (int i = 0; i < 4; i++) {
            int c = tid + i * 256;
            int row = c >> 3, cc = c & 7;
            cpa16(&An[row * TH + cc * 8], &Asrc[(size_t)(bm + row) * a_stride + k0 + cc * 8]);
            cpa16(&Bn[row * TH + cc * 8], &Bsrc[(size_t)(bn + row) * b_stride + k0 + cc * 8]);
        }
    };

    stage(0); cpa_commit();

    const int lane = tid & 31;
    const int wid  = tid >> 5;
    const int wm   = (wid >> 2) * 64;
    const int wn   = (wid & 3) * 32;
    const int q8   = lane >> 3;
    const int r8   = lane & 7;

    for (int kt = 0; kt < NK; kt++) {
        cpa_wait0();
        __syncthreads();
        if (kt + 1 < NK) {
            stage(kt + 1);
            cpa_commit();
        }

        const unsigned* A32 = (const unsigned*)(Ah + (kt & 1) * TSZ);
        const unsigned* B32 = (const unsigned*)(Bh + (kt & 1) * TSZ);
#pragma unroll
        for (int kc = 0; kc < 4; kc++) {
            const int kb = kc * 8;
            unsigned af[4][4], bf[4][2];
#pragma unroll
            for (int mi = 0; mi < 4; mi++) {
                const int row = wm + mi * 16 + (q8 & 1) * 8 + r8;
                const int col = kb + (q8 >> 1) * 4;
                ldsm4(af[mi][0], af[mi][1], af[mi][2], af[mi][3], A32 + row * TH32 + col);
            }
#pragma unroll
            for (int njp = 0; njp < 4; njp += 2) {
                const int row = wn + njp * 8 + (q8 >> 1) * 8 + r8;
                const int col = kb + (q8 & 1) * 4;
                ldsm4(bf[njp][0], bf[njp][1], bf[njp + 1][0], bf[njp + 1][1],
                      B32 + row * TH32 + col);
            }
#pragma unroll
            for (int mi = 0; mi < 4; mi++)
#pragma unroll
                for (int nj = 0; nj < 4; nj++)
                    mma16(acc[mi][nj], af[mi][0], af[mi][1], af[mi][2], af[mi][3],
                          bf[nj][0], bf[nj][1]);
        }
    }
}

// ---------------------------------------------------------------------------
// QKV GEMM: q/k [B,H,S,hd]; v TRANSPOSED [B,H,hd,S]
// ---------------------------------------------------------------------------
__global__ __launch_bounds__(256, 2) void qkv_gemm(const float* __restrict__ bias)
{
    extern __shared__ __half shq[];
    float acc[4][4][4];
#pragma unroll
    for (int mi = 0; mi < 4; mi++)
#pragma unroll
        for (int nj = 0; nj < 4; nj++)
#pragma unroll
            for (int t = 0; t < 4; t++) acc[mi][nj][t] = 0.f;

    const int bm = blockIdx.y * 128;
    const int bn = blockIdx.x * 128;
    gemm128(g_x, 1024, g_wa, 1024, bm, bn, shq, acc);

    const int lane = threadIdx.x & 31;
    const int wid  = threadIdx.x >> 5;
    const int g    = lane >> 2;
    const int tg   = lane & 3;
    const int wm   = (wid >> 2) * 64;
    const int wn   = (wid & 3) * 32;

#pragma unroll
    for (int mi = 0; mi < 4; mi++) {
#pragma unroll
        for (int nj = 0; nj < 4; nj++) {
#pragma unroll
            for (int t = 0; t < 4; t++) {
                const int m = bm + wm + mi * 16 + g + ((t >= 2) ? 8 : 0);
                const int n = bn + wn + nj * 8 + 2 * tg + (t & 1);
                const float v = acc[mi][nj][t] + bias[n];
                const int bidx = m >> 11;
                const int s = m & 2047;
                const int which = n >> 10;
                const int jj = n & 1023;
                const int h = jj >> 6;
                const int d = jj & 63;
                if (which == 0)
                    g_q[(size_t)((bidx * HH + h) * SS + s) * HD + d] = __float2half_rn(v);
                else if (which == 1)
                    g_k[(size_t)((bidx * HH + h) * SS + s) * HD + d] = __float2half_rn(v);
                else
                    g_v[(size_t)((bidx * HH + h) * HD + d) * SS + s] = __float2half_rn(v);
            }
        }
    }
}

// ---------------------------------------------------------------------------
// Flash attention pass 1 only: O, m, 1/l. LPT.
// ---------------------------------------------------------------------------
#define PS_H 136
#define PS_H32 68
#define PSSZ (128*PS_H)
#define KH 72
#define KH32 36
#define KSZH (128*KH)
#define VT_H 136
#define VT_H32 68
#define VTSZ (64*VT_H)
#define ATT_SMEM_BYTES ((PSSZ + 2*KSZH + 2*VTSZ) * 2)

__global__ __launch_bounds__(256, 2) void attn_kernel()
{
    extern __shared__ __half smh[];
    __half* Ps = smh;                     // [128][PS_H]
    __half* Kh = smh + PSSZ;              // [2][128][KH]
    __half* VT = Kh + 2 * KSZH;           // [2][64][VT_H]

    const int tid  = threadIdx.x;
    const int lane = tid & 31;
    const int wid  = tid >> 5;
    const int g    = lane >> 2;
    const int tg   = lane & 3;
    const int qw   = wid * 16;
    const int q8   = lane >> 3;
    const int r8   = lane & 7;

    const int b  = blockIdx.z;
    const int h  = blockIdx.y;
    const int qt = (gridDim.x - 1) - blockIdx.x;   // LPT
    const int q0 = qt * 128;

    const __half* Qbh = g_q + (size_t)((b * HH + h) * SS) * HD;
    const __half* Kbh = g_k + (size_t)((b * HH + h) * SS) * HD;
    const __half* Vbt = g_v + (size_t)((b * HH + h) * HD) * SS;

#pragma unroll
    for (int i = 0; i < 4; i++) {
        int c = tid + i * 256;
        int row = c >> 3, cc = c & 7;
        cpa16(&Kh[row * KH + cc * 8], &Kbh[(size_t)row * HD + cc * 8]);
    }
#pragma unroll
    for (int i = 0; i < 4; i++) {
        int c = tid + i * 256;
        int row = c >> 4, cc = c & 15;
        cpa16(&VT[row * VT_H + cc * 8], &Vbt[(size_t)row * SS + cc * 8]);
    }
    cpa_commit();

    unsigned qa[4][4];
    {
        const unsigned* q0p = (const unsigned*)(Qbh + (size_t)(q0 + qw + g) * HD);
        const unsigned* q1p = (const unsigned*)(Qbh + (size_t)(q0 + qw + g + 8) * HD);
#pragma unroll
        for (int kc = 0; kc < 4; kc++) {
            qa[kc][0] = q0p[kc * 8 + tg    ];
            qa[kc][1] = q1p[kc * 8 + tg    ];
            qa[kc][2] = q0p[kc * 8 + 4 + tg];
            qa[kc][3] = q1p[kc * 8 + 4 + tg];
        }
    }

    float m0 = -1e30f, m1 = -1e30f, l0 = 0.f, l1 = 0.f;
    float o[8][4];
#pragma unroll
    for (int nf = 0; nf < 8; nf++)
#pragma unroll
        for (int t = 0; t < 4; t++) o[nf][t] = 0.f;

    const int nkt  = qt + 1;
    const int row0 = q0 + qw + g;
    const int row1 = row0 + 8;

    for (int kt = 0; kt < nkt; kt++) {
        cpa_wait0();
        __syncthreads();

        if (kt + 1 < nkt) {
            const int nb = (kt + 1) * 128;
            __half* Kn = Kh + ((kt + 1) & 1) * KSZH;
            __half* Vn = VT + ((kt + 1) & 1) * VTSZ;
#pragma unroll
            for (int i = 0; i < 4; i++) {
                int c = tid + i * 256;
                int row = c >> 3, cc = c & 7;
                cpa16(&Kn[row * KH + cc * 8], &Kbh[(size_t)(nb + row) * HD + cc * 8]);
            }
#pragma unroll
            for (int i = 0; i < 4; i++) {
                int c = tid + i * 256;
                int row = c >> 4, cc = c & 15;
                cpa16(&Vn[row * VT_H + cc * 8], &Vbt[(size_t)row * SS + nb + cc * 8]);
            }
            cpa_commit();
        }

        const unsigned* K32 = (const unsigned*)(Kh + (kt & 1) * KSZH);
        const int kbase = kt * 128;

        float s[16][4];
#pragma unroll
        for (int nf = 0; nf < 16; nf++)
#pragma unroll
            for (int t = 0; t < 4; t++) s[nf][t] = 0.f;
#pragma unroll
        for (int kc = 0; kc < 4; kc++) {
#pragma unroll
            for (int nfp = 0; nfp < 16; nfp += 2) {
                unsigned b00, b01, b10, b11;
                const int row = nfp * 8 + (q8 >> 1) * 8 + r8;
                const int col = kc * 8 + (q8 & 1) * 4;
                ldsm4(b00, b01, b10, b11, K32 + row * KH32 + col);
                mma16(s[nfp    ], qa[kc][0], qa[kc][1], qa[kc][2], qa[kc][3], b00, b01);
                mma16(s[nfp + 1], qa[kc][0], qa[kc][1], qa[kc][2], qa[kc][3], b10, b11);
            }
        }

        const bool diag = (kt == qt);
        float mx0 = -1e30f, mx1 = -1e30f;
#pragma unroll
        for (int nf = 0; nf < 16; nf++) {
            const int col = kbase + nf * 8 + 2 * tg;
            float v0 = s[nf][0] * 0.125f;
            float v1 = s[nf][1] * 0.125f;
            float v2 = s[nf][2] * 0.125f;
            float v3 = s[nf][3] * 0.125f;
            if (diag) {
                if (col     > row0) v0 = -1e30f;
                if (col + 1 > row0) v1 = -1e30f;
                if (col     > row1) v2 = -1e30f;
                if (col + 1 > row1) v3 = -1e30f;
            }
            s[nf][0] = v0; s[nf][1] = v1; s[nf][2] = v2; s[nf][3] = v3;
            mx0 = fmaxf(mx0, fmaxf(v0, v1));
            mx1 = fmaxf(mx1, fmaxf(v2, v3));
        }
        mx0 = fmaxf(mx0, __shfl_xor_sync(0xffffffffu, mx0, 1));
        mx0 = fmaxf(mx0, __shfl_xor_sync(0xffffffffu, mx0, 2));
        mx1 = fmaxf(mx1, __shfl_xor_sync(0xffffffffu, mx1, 1));
        mx1 = fmaxf(mx1, __shfl_xor_sync(0xffffffffu, mx1, 2));

        const float mn0 = fmaxf(m0, mx0);
        const float mn1 = fmaxf(m1, mx1);
        const float al0 = __expf(m0 - mn0);
        const float al1 = __expf(m1 - mn1);

        float rs0 = 0.f, rs1 = 0.f;
        __half2* Pp = (__half2*)Ps;
#pragma unroll
        for (int nf = 0; nf < 16; nf++) {
            const float p0 = __expf(s[nf][0] - mn0);
            const float p1 = __expf(s[nf][1] - mn0);
            const float p2 = __expf(s[nf][2] - mn1);
            const float p3 = __expf(s[nf][3] - mn1);
            rs0 += p0 + p1;
            rs1 += p2 + p3;
            Pp[(qw + g    ) * (PS_H/2) + nf * 4 + tg] = __floats2half2_rn(p0, p1);
            Pp[(qw + g + 8) * (PS_H/2) + nf * 4 + tg] = __floats2half2_rn(p2, p3);
        }
        rs0 += __shfl_xor_sync(0xffffffffu, rs0, 1);
        rs0 += __shfl_xor_sync(0xffffffffu, rs0, 2);
        rs1 += __shfl_xor_sync(0xffffffffu, rs1, 1);
        rs1 += __shfl_xor_sync(0xffffffffu, rs1, 2);

        m0 = mn0; m1 = mn1;
        l0 = l0 * al0 + rs0;
        l1 = l1 * al1 + rs1;
#pragma unroll
        for (int nf = 0; nf < 8; nf++) {
            o[nf][0] *= al0; o[nf][1] *= al0;
            o[nf][2] *= al1; o[nf][3] *= al1;
        }

        const unsigned* P32  = (const unsigned*)Ps;
        const unsigned* VT32 = (const unsigned*)(VT + (kt & 1) * VTSZ);
#pragma unroll
        for (int kc = 0; kc < 8; kc++) {
            unsigned a0, a1, a2, a3;
            {
                const int row = qw + (q8 & 1) * 8 + r8;
                const int col = kc * 8 + (q8 >> 1) * 4;
                ldsm4(a0, a1, a2, a3, P32 + row * PS_H32 + col);
            }
#pragma unroll
            for (int nfp = 0; nfp < 8; nfp += 2) {
                unsigned b00, b01, b10, b11;
                const int row = nfp * 8 + (q8 >> 1) * 8 + r8;
                const int col = kc * 8 + (q8 & 1) * 4;
                ldsm4(b00, b01, b10, b11, VT32 + row * VT_H32 + col);
                mma16(o[nfp    ], a0, a1, a2, a3, b00, b01);
                mma16(o[nfp + 1], a0, a1, a2, a3, b10, b11);
            }
        }
    }

    const float il0 = 1.0f / l0;
    const float il1 = 1.0f / l1;
    {
        const int orow = b * SS + q0 + qw + g;
#pragma unroll
        for (int nf = 0; nf < 8; nf++) {
            const int col = h * HD + nf * 8 + 2 * tg;
            __half2* d0 = (__half2*)&g_ao[(size_t)orow * DD + col];
            __half2* d1 = (__half2*)&g_ao[(size_t)(orow + 8) * DD + col];
            *d0 = __floats2half2_rn(o[nf][0] * il0, o[nf][1] * il0);
            *d1 = __floats2half2_rn(o[nf][2] * il1, o[nf][3] * il1);
        }
        if (tg == 0) {
            const size_t mlbase = (size_t)(b * HH + h) * SS;
            g_ml[mlbase + q0 + qw + g    ] = make_float2(m0, il0);
            g_ml[mlbase + q0 + qw + g + 8] = make_float2(m1, il1);
        }
    }
}

// ---------------------------------------------------------------------------
// Epilogue: CTA 0..255 = proj tiles; 256..4351 = weight tile PAIRS (128x256):
// double-buffered K across the pair, zero/recompute per subtile.
// ---------------------------------------------------------------------------
__global__ __launch_bounds__(256, 2) void epilogue(const float* __restrict__ bias,
                                                   float* __restrict__ out)
{
    extern __shared__ __half shq[];
    const int tid  = threadIdx.x;
    const int lane = tid & 31;
    const int wid  = tid >> 5;
    const int g    = lane >> 2;
    const int tg   = lane & 3;
    const int idx  = blockIdx.x;

    if (idx < 256) {
        float acc[4][4][4];
#pragma unroll
        for (int mi = 0; mi < 4; mi++)
#pragma unroll
            for (int nj = 0; nj < 4; nj++)
#pragma unroll
                for (int t = 0; t < 4; t++) acc[mi][nj][t] = 0.f;

        const int bm = (idx >> 3) * 128;
        const int bn = (idx & 7) * 128;
        gemm128(g_ao, 1024, g_wp, 1024, bm, bn, shq, acc);

        const int wm = (wid >> 2) * 64;
        const int wn = (wid & 3) * 32;
#pragma unroll
        for (int mi = 0; mi < 4; mi++) {
#pragma unroll
            for (int nj = 0; nj < 4; nj++) {
#pragma unroll
                for (int t = 0; t < 4; t++) {
                    const int m = bm + wm + mi * 16 + g + ((t >= 2) ? 8 : 0);
                    const int n = bn + wn + nj * 8 + 2 * tg + (t & 1);
                    out[(size_t)m * DD + n] = acc[mi][nj][t] + bias[n];
                }
            }
        }
        return;
    }

    // weight tile pair: 128 rows x 256 cols, subtiles kt0 = 2*ktp, kt1 = kt0+1
    const int w   = idx - 256;
    const int bh  = w >> 7;           // 32 (b,h) x 128 pairs
    const int t7  = w & 127;
    const int qt  = t7 >> 3;
    const int ktp = t7 & 7;
    const int kt0 = ktp * 2;
    const int b   = bh >> 4;
    const int h   = bh & 15;
    const int q0  = qt * 128;

    float* attn = out + (size_t)MM * DD;
    float* base = attn + ((size_t)((b * HH + h) * SS) + q0) * SS;

    if (kt0 > qt) {
        // both subtiles strictly upper: pure zero 128x256
        const float4 z = make_float4(0.f, 0.f, 0.f, 0.f);
        float* dst = base + kt0 * 128;
#pragma unroll
        for (int i = 0; i < 32; i++) {
            int c = tid + i * 256;
            int row = c >> 6, c4 = c & 63;
            stcs4(&dst[(size_t)row * SS + c4 * 4], z);
        }
        return;
    }

    const __half* Kbh = g_k + (size_t)((b * HH + h) * SS) * HD;
    __half* Kh0 = shq;
    __half* Kh1 = shq + KSZH;

    // stage K for both subtiles (skip upper), one commit group each
#pragma unroll
    for (int t = 0; t < 2; t++) {
        const int kt = kt0 + t;
        if (kt <= qt) {
            __half* Kd = t ? Kh1 : Kh0;
            const int kb = kt * 128;
#pragma unroll
            for (int i = 0; i < 4; i++) {
                int c = tid + i * 256;
                int row = c >> 3, cc = c & 7;
                cpa16(&Kd[row * KH + cc * 8], &Kbh[(size_t)(kb + row) * HD + cc * 8]);
            }
        }
        cpa_commit();
    }

    const __half* Qbh = g_q + (size_t)((b * HH + h) * SS) * HD;
    const int qw = wid * 16;
    unsigned qa[4][4];
    {
        const unsigned* q0p = (const unsigned*)(Qbh + (size_t)(q0 + qw + g) * HD);
        const unsigned* q1p = (const unsigned*)(Qbh + (size_t)(q0 + qw + g + 8) * HD);
#pragma unroll
        for (int kc = 0; kc < 4; kc++) {
            qa[kc][0] = q0p[kc * 8 + tg    ];
            qa[kc][1] = q1p[kc * 8 + tg    ];
            qa[kc][2] = q0p[kc * 8 + 4 + tg];
            qa[kc][3] = q1p[kc * 8 + 4 + tg];
        }
    }

    const size_t mlbase = (size_t)(b * HH + h) * SS;
    const float2 ml0 = g_ml[mlbase + q0 + qw + g    ];
    const float2 ml1 = g_ml[mlbase + q0 + qw + g + 8];

    const int q8 = lane >> 3;
    const int r8 = lane & 7;
    const int row0 = q0 + qw + g;
    const int row1 = row0 + 8;

#pragma unroll
    for (int t = 0; t < 2; t++) {
        const int kt = kt0 + t;
        const int kbase = kt * 128;
        float* dst = base + kbase;
        float* w0p = dst + (size_t)(qw + g) * SS;
        float* w1p = dst + (size_t)(qw + g + 8) * SS;

        if (t == 0) cpa_wait1(); else cpa_wait0();
        __syncthreads();

        if (kt > qt) {
            // upper subtile: zero 128x128
            const float4 z = make_float4(0.f, 0.f, 0.f, 0.f);
#pragma unroll
            for (int i = 0; i < 16; i++) {
                int c = tid + i * 256;
                int row = c >> 5, c4 = c & 31;
                stcs4(&dst[(size_t)row * SS + c4 * 4], z);
            }
            continue;
        }

        const unsigned* K32 = (const unsigned*)(t ? Kh1 : Kh0);

        float s[16][4];
#pragma unroll
        for (int nf = 0; nf < 16; nf++)
#pragma unroll
            for (int t2 = 0; t2 < 4; t2++) s[nf][t2] = 0.f;
#pragma unroll
        for (int kc = 0; kc < 4; kc++) {
#pragma unroll
            for (int nfp = 0; nfp < 16; nfp += 2) {
                unsigned b00, b01, b10, b11;
                const int row = nfp * 8 + (q8 >> 1) * 8 + r8;
                const int col = kc * 8 + (q8 & 1) * 4;
                ldsm4(b00, b01, b10, b11, K32 + row * KH32 + col);
                mma16(s[nfp    ], qa[kc][0], qa[kc][1], qa[kc][2], qa[kc][3], b00, b01);
                mma16(s[nfp + 1], qa[kc][0], qa[kc][1], qa[kc][2], qa[kc][3], b10, b11);
            }
        }

        const bool diag = (kt == qt);
#pragma unroll
        for (int nf = 0; nf < 16; nf++) {
            const int coll = nf * 8 + 2 * tg;
            const int col  = kbase + coll;
            float w0 = __expf(s[nf][0] * 0.125f - ml0.x) * ml0.y;
            float w1 = __expf(s[nf][1] * 0.125f - ml0.x) * ml0.y;
            float w2 = __expf(s[nf][2] * 0.125f - ml1.x) * ml1.y;
            float w3 = __expf(s[nf][3] * 0.125f - ml1.x) * ml1.y;
            if (diag) {
                if (col     > row0) w0 = 0.f;
                if (col + 1 > row0) w1 = 0.f;
                if (col     > row1) w2 = 0.f;
                if (col + 1 > row1) w3 = 0.f;
            }
            stcs2(&w0p[coll], w0, w1);
            stcs2(&w1p[coll], w2, w3);
        }
    }
}

// ---------------------------------------------------------------------------
extern "C" void kernel_launch(void* const* d_in, const int* in_sizes, int n_in,
                              void* d_out, int out_size)
{
    const float* x      = (const float*)d_in[0];
    const float* W_attn = (const float*)d_in[1];
    const float* b_attn = (const float*)d_in[2];
    const float* W_proj = (const float*)d_in[3];
    const float* b_proj = (const float*)d_in[4];
    float* out = (float*)d_out;

    cudaFuncSetAttribute(qkv_gemm,
                         cudaFuncAttributeMaxDynamicSharedMemorySize, GEMM_SMEM_BYTES);
    cudaFuncSetAttribute(epilogue,
                         cudaFuncAttributeMaxDynamicSharedMemorySize, GEMM_SMEM_BYTES);
    cudaFuncSetAttribute(attn_kernel,
                         cudaFuncAttributeMaxDynamicSharedMemorySize, ATT_SMEM_BYTES);

    preproc<<<5120, 256>>>(x, W_attn, W_proj);
    qkv_gemm<<<dim3(24, 32), 256, GEMM_SMEM_BYTES>>>(b_attn);
    attn_kernel<<<dim3(SS / 128, HH, BB), 256, ATT_SMEM_BYTES>>>();
    epilogue<<<256 + 4096, 256, GEMM_SMEM_BYTES>>>(b_proj, out);
}